// round 3
// baseline (speedup 1.0000x reference)
#include <cuda_runtime.h>

// YOLOv1 loss — single fused kernel, one cell per thread.
// pred, target: float32 [batch*7*7*30]; out: 5 float32.

static constexpr int CH        = 30;
static constexpr int CELLS_PB  = 49;
static constexpr int NTHREADS  = 256;
static constexpr int MAXBLOCKS = 16384;

__device__ float        g_part[MAXBLOCKS][4];
__device__ unsigned int g_count = 0;

__device__ __forceinline__ float warp_sum(float v) {
#pragma unroll
    for (int o = 16; o > 0; o >>= 1) v += __shfl_down_sync(0xffffffffu, v, o);
    return v;
}
__device__ __forceinline__ double warp_sum_d(double v) {
#pragma unroll
    for (int o = 16; o > 0; o >>= 1) v += __shfl_down_sync(0xffffffffu, v, o);
    return v;
}

__device__ __forceinline__ float iou_f(float x1, float y1, float w1, float h1,
                                       float x2, float y2, float w2, float h2) {
    float area1 = w1 * h1;
    float area2 = w2 * h2;
    float ml = fmaxf(x1 - w1 * 0.5f, x2 - w2 * 0.5f);
    float mr = fminf(x1 + w1 * 0.5f, x2 + w2 * 0.5f);
    float mt = fmaxf(y1 - h1 * 0.5f, y2 - h2 * 0.5f);
    float mb = fminf(y1 + h1 * 0.5f, y2 + h2 * 0.5f);
    float iw = fmaxf(mr - ml, 0.0f);
    float ih = fmaxf(mb - mt, 0.0f);
    float inter = iw * ih;
    float uni   = area1 + area2 - inter;
    return (inter > 0.0f) ? (inter / uni) : 0.0f;
}

__global__ void __launch_bounds__(NTHREADS)
yolo_fused_kernel(const float* __restrict__ pred,
                  const float* __restrict__ target,
                  int ncells, float inv_bs,
                  float* __restrict__ out) {
    float s_coord = 0.0f, s_obj = 0.0f, s_noobj = 0.0f, s_class = 0.0f;

    int cell = blockIdx.x * blockDim.x + threadIdx.x;
    if (cell < ncells) {
        const float2* p2 = reinterpret_cast<const float2*>(pred   + (size_t)cell * CH);
        const float2* t2 = reinterpret_cast<const float2*>(target + (size_t)cell * CH);

        // Head channels 0..9 (5 float2 each stream) — only 20 floats live.
        float pr[10], tg[10];
#pragma unroll
        for (int i = 0; i < 5; i++) {
            float2 v = __ldg(p2 + i);
            pr[2 * i] = v.x; pr[2 * i + 1] = v.y;
            float2 w = __ldg(t2 + i);
            tg[2 * i] = w.x; tg[2 * i + 1] = w.y;
        }

        // Class channels 10..29 — streamed, consumed immediately.
        float cls = 0.0f;
#pragma unroll
        for (int i = 5; i < 15; i++) {
            float2 v = __ldg(p2 + i);
            float2 w = __ldg(t2 + i);
            float d0 = v.x - w.x;
            float d1 = v.y - w.y;
            cls += d0 * d0 + d1 * d1;
        }

        float obj_f = (tg[0] == 1.0f) ? 1.0f : 0.0f;

        float iou1 = iou_f(pr[1], pr[2], pr[3], pr[4], tg[1], tg[2], tg[3], tg[4]);
        float iou2 = iou_f(tg[6], tg[7], tg[8], tg[9], tg[1], tg[2], tg[3], tg[4]);
        bool r = iou1 > iou2;

        float px = r ? pr[1] : pr[6], py = r ? pr[2] : pr[7];
        float tx = r ? tg[1] : tg[6], ty = r ? tg[2] : tg[7];
        float pw = r ? pr[3] : pr[8], ph = r ? pr[4] : pr[9];
        float tw = r ? tg[3] : tg[8], th = r ? tg[4] : tg[9];

        float dx = px - tx, dy = py - ty;
        float cell_xy = dx * dx + dy * dy;
        float dw = sqrtf(pw) - sqrtf(tw);
        float dh = sqrtf(ph) - sqrtf(th);
        float cell_wh = dw * dw + dh * dh;

        float conf_resp  = r ? pr[0] : pr[5];
        float iou_resp   = r ? iou1  : iou2;
        float d_obj      = conf_resp - iou_resp;

        float conf_other = r ? pr[5] : pr[0];
        float noobj = obj_f * (conf_other * conf_other)
                    + (1.0f - obj_f) * (pr[0] * pr[0] + pr[5] * pr[5]);

        s_coord = obj_f * (cell_xy + cell_wh);
        s_obj   = obj_f * (d_obj * d_obj);
        s_noobj = noobj;
        s_class = obj_f * cls;
    }

    // ---- intra-block reduction ----
    s_coord = warp_sum(s_coord);
    s_obj   = warp_sum(s_obj);
    s_noobj = warp_sum(s_noobj);
    s_class = warp_sum(s_class);

    __shared__ float sm[NTHREADS / 32][4];
    int lane = threadIdx.x & 31;
    int w    = threadIdx.x >> 5;
    if (lane == 0) {
        sm[w][0] = s_coord; sm[w][1] = s_obj;
        sm[w][2] = s_noobj; sm[w][3] = s_class;
    }
    __syncthreads();

    __shared__ bool is_last;
    if (threadIdx.x == 0) is_last = false;

    if (w == 0) {
        float a = (lane < NTHREADS / 32) ? sm[lane][0] : 0.0f;
        float b = (lane < NTHREADS / 32) ? sm[lane][1] : 0.0f;
        float c = (lane < NTHREADS / 32) ? sm[lane][2] : 0.0f;
        float d = (lane < NTHREADS / 32) ? sm[lane][3] : 0.0f;
        a = warp_sum(a); b = warp_sum(b); c = warp_sum(c); d = warp_sum(d);
        if (lane == 0) {
            g_part[blockIdx.x][0] = a;
            g_part[blockIdx.x][1] = b;
            g_part[blockIdx.x][2] = c;
            g_part[blockIdx.x][3] = d;
            __threadfence();
            unsigned int ticket = atomicAdd(&g_count, 1u);
            is_last = (ticket == gridDim.x - 1);
        }
    }
    __syncthreads();

    // ---- last block folds partials (fp64, fixed order -> deterministic) ----
    if (is_last) {
        const volatile float* gp = &g_part[0][0];
        double v0 = 0.0, v1 = 0.0, v2 = 0.0, v3 = 0.0;
        for (int i = threadIdx.x; i < (int)gridDim.x; i += NTHREADS) {
            v0 += (double)gp[4 * i + 0];
            v1 += (double)gp[4 * i + 1];
            v2 += (double)gp[4 * i + 2];
            v3 += (double)gp[4 * i + 3];
        }
        v0 = warp_sum_d(v0); v1 = warp_sum_d(v1);
        v2 = warp_sum_d(v2); v3 = warp_sum_d(v3);

        __shared__ double smd[NTHREADS / 32][4];
        if (lane == 0) { smd[w][0] = v0; smd[w][1] = v1; smd[w][2] = v2; smd[w][3] = v3; }
        __syncthreads();
        if (w == 0) {
            double a = (lane < NTHREADS / 32) ? smd[lane][0] : 0.0;
            double b = (lane < NTHREADS / 32) ? smd[lane][1] : 0.0;
            double c = (lane < NTHREADS / 32) ? smd[lane][2] : 0.0;
            double d = (lane < NTHREADS / 32) ? smd[lane][3] : 0.0;
            a = warp_sum_d(a); b = warp_sum_d(b);
            c = warp_sum_d(c); d = warp_sum_d(d);
            if (lane == 0) {
                double coord = 5.0 * a;   // LAMBDA_COORD
                double objl  = b;
                double noobj = 0.5 * c;   // LAMBDA_NOOBJ
                double cls   = d;
                out[0] = (float)(coord * (double)inv_bs);
                out[1] = (float)(objl  * (double)inv_bs);
                out[2] = (float)(noobj * (double)inv_bs);
                out[3] = (float)(cls   * (double)inv_bs);
                out[4] = (float)((coord + objl + noobj + cls) * (double)inv_bs);
                g_count = 0;              // reset for next graph replay
            }
        }
    }
}

extern "C" void kernel_launch(void* const* d_in, const int* in_sizes, int n_in,
                              void* d_out, int out_size) {
    const float* pred   = (const float*)d_in[0];
    const float* target = (const float*)d_in[1];
    float* out = (float*)d_out;

    int total  = in_sizes[0];                  // batch * 49 * 30
    int ncells = total / CH;                   // batch * 49
    int batch  = ncells / CELLS_PB;
    int nblocks = (ncells + NTHREADS - 1) / NTHREADS;   // 3136 for batch=16384
    float inv_bs = 1.0f / (float)batch;

    yolo_fused_kernel<<<nblocks, NTHREADS>>>(pred, target, ncells, inv_bs, out);
}

// round 4
// speedup vs baseline: 1.3415x; 1.3415x over previous
#include <cuda_runtime.h>

// YOLOv1 loss — smem-staged coalesced streaming, single fused kernel.
// pred, target: float32 [batch*7*7*30]; out: 5 float32.

static constexpr int CH          = 30;
static constexpr int CELLS_PB    = 49;
static constexpr int NT          = 256;          // threads per block
static constexpr int CELLS_CHUNK = 256;          // cells staged per block iteration
static constexpr int F2_STREAM   = CELLS_CHUNK * CH / 2;   // 3840 float2 per stream
static constexpr int SMEM_BYTES  = 2 * F2_STREAM * 8;      // 61440 B
static constexpr int MAXBLOCKS   = 4096;
static constexpr int TARGET_BLOCKS = 448;        // ~3 blocks/SM, single wave

__device__ float        g_part[MAXBLOCKS][4];
__device__ unsigned int g_count = 0;

__device__ __forceinline__ float warp_sum(float v) {
#pragma unroll
    for (int o = 16; o > 0; o >>= 1) v += __shfl_down_sync(0xffffffffu, v, o);
    return v;
}
__device__ __forceinline__ double warp_sum_d(double v) {
#pragma unroll
    for (int o = 16; o > 0; o >>= 1) v += __shfl_down_sync(0xffffffffu, v, o);
    return v;
}

__device__ __forceinline__ float iou_f(float x1, float y1, float w1, float h1,
                                       float x2, float y2, float w2, float h2) {
    float area1 = w1 * h1;
    float area2 = w2 * h2;
    float ml = fmaxf(x1 - w1 * 0.5f, x2 - w2 * 0.5f);
    float mr = fminf(x1 + w1 * 0.5f, x2 + w2 * 0.5f);
    float mt = fmaxf(y1 - h1 * 0.5f, y2 - h2 * 0.5f);
    float mb = fminf(y1 + h1 * 0.5f, y2 + h2 * 0.5f);
    float iw = fmaxf(mr - ml, 0.0f);
    float ih = fmaxf(mb - mt, 0.0f);
    float inter = iw * ih;
    float uni   = area1 + area2 - inter;
    return (inter > 0.0f) ? (inter / uni) : 0.0f;
}

__global__ void __launch_bounds__(NT)
yolo_staged_kernel(const float* __restrict__ pred,
                   const float* __restrict__ target,
                   int ncells, int nchunks, float inv_bs,
                   float* __restrict__ out) {
    extern __shared__ float2 s2[];   // [0..3839] pred chunk, [3840..7679] target chunk
    const int tid = threadIdx.x;

    float s_coord = 0.0f, s_obj = 0.0f, s_noobj = 0.0f, s_class = 0.0f;

    for (int chunk = blockIdx.x; chunk < nchunks; chunk += gridDim.x) {
        const int cell0 = chunk * CELLS_CHUNK;
        const float2* pg = reinterpret_cast<const float2*>(pred)   + (size_t)cell0 * (CH / 2);
        const float2* tg_g = reinterpret_cast<const float2*>(target) + (size_t)cell0 * (CH / 2);

        const bool full = (cell0 + CELLS_CHUNK) <= ncells;

        if (full) {
            // Coalesced staging: 30 LDG.64 / thread, warp = 256B contiguous.
#pragma unroll
            for (int k = 0; k < 15; k++)
                s2[k * NT + tid] = __ldg(pg + k * NT + tid);
#pragma unroll
            for (int k = 0; k < 15; k++)
                s2[F2_STREAM + k * NT + tid] = __ldg(tg_g + k * NT + tid);
        } else {
            int rem_f2 = (ncells - cell0) * (CH / 2);   // remaining float2 in this chunk
            for (int idx = tid; idx < rem_f2; idx += NT) {
                s2[idx]             = __ldg(pg + idx);
                s2[F2_STREAM + idx] = __ldg(tg_g + idx);
            }
        }
        __syncthreads();

        int cell = cell0 + tid;
        if (cell < ncells) {
            const float2* sp = s2 + (size_t)tid * 15;              // pred cell (15 float2)
            const float2* st = s2 + F2_STREAM + (size_t)tid * 15;  // target cell

            float pr[10], tg[10];
#pragma unroll
            for (int i = 0; i < 5; i++) {
                float2 v = sp[i];
                pr[2 * i] = v.x; pr[2 * i + 1] = v.y;
                float2 w = st[i];
                tg[2 * i] = w.x; tg[2 * i + 1] = w.y;
            }
            float cls = 0.0f;
#pragma unroll
            for (int i = 5; i < 15; i++) {
                float2 v = sp[i];
                float2 w = st[i];
                float d0 = v.x - w.x;
                float d1 = v.y - w.y;
                cls += d0 * d0 + d1 * d1;
            }

            float obj_f = (tg[0] == 1.0f) ? 1.0f : 0.0f;

            float iou1 = iou_f(pr[1], pr[2], pr[3], pr[4], tg[1], tg[2], tg[3], tg[4]);
            float iou2 = iou_f(tg[6], tg[7], tg[8], tg[9], tg[1], tg[2], tg[3], tg[4]);
            bool r = iou1 > iou2;

            float px = r ? pr[1] : pr[6], py = r ? pr[2] : pr[7];
            float tx = r ? tg[1] : tg[6], ty = r ? tg[2] : tg[7];
            float pw = r ? pr[3] : pr[8], ph = r ? pr[4] : pr[9];
            float tw = r ? tg[3] : tg[8], th = r ? tg[4] : tg[9];

            float dx = px - tx, dy = py - ty;
            float cell_xy = dx * dx + dy * dy;
            float dw = sqrtf(pw) - sqrtf(tw);
            float dh = sqrtf(ph) - sqrtf(th);
            float cell_wh = dw * dw + dh * dh;

            float conf_resp  = r ? pr[0] : pr[5];
            float iou_resp   = r ? iou1  : iou2;
            float d_obj      = conf_resp - iou_resp;

            float conf_other = r ? pr[5] : pr[0];
            float noobj = obj_f * (conf_other * conf_other)
                        + (1.0f - obj_f) * (pr[0] * pr[0] + pr[5] * pr[5]);

            s_coord += obj_f * (cell_xy + cell_wh);
            s_obj   += obj_f * (d_obj * d_obj);
            s_noobj += noobj;
            s_class += obj_f * cls;
        }
        __syncthreads();   // smem reused next iteration
    }

    // ---- intra-block reduction ----
    s_coord = warp_sum(s_coord);
    s_obj   = warp_sum(s_obj);
    s_noobj = warp_sum(s_noobj);
    s_class = warp_sum(s_class);

    __shared__ float sm[NT / 32][4];
    int lane = threadIdx.x & 31;
    int w    = threadIdx.x >> 5;
    if (lane == 0) {
        sm[w][0] = s_coord; sm[w][1] = s_obj;
        sm[w][2] = s_noobj; sm[w][3] = s_class;
    }
    __syncthreads();

    __shared__ bool is_last;
    if (threadIdx.x == 0) is_last = false;

    if (w == 0) {
        float a = (lane < NT / 32) ? sm[lane][0] : 0.0f;
        float b = (lane < NT / 32) ? sm[lane][1] : 0.0f;
        float c = (lane < NT / 32) ? sm[lane][2] : 0.0f;
        float d = (lane < NT / 32) ? sm[lane][3] : 0.0f;
        a = warp_sum(a); b = warp_sum(b); c = warp_sum(c); d = warp_sum(d);
        if (lane == 0) {
            g_part[blockIdx.x][0] = a;
            g_part[blockIdx.x][1] = b;
            g_part[blockIdx.x][2] = c;
            g_part[blockIdx.x][3] = d;
            __threadfence();
            unsigned int ticket = atomicAdd(&g_count, 1u);
            is_last = (ticket == gridDim.x - 1);
        }
    }
    __syncthreads();

    // ---- last block folds partials (fp64, fixed order -> deterministic) ----
    if (is_last) {
        const volatile float* gp = &g_part[0][0];
        double v0 = 0.0, v1 = 0.0, v2 = 0.0, v3 = 0.0;
        for (int i = threadIdx.x; i < (int)gridDim.x; i += NT) {
            v0 += (double)gp[4 * i + 0];
            v1 += (double)gp[4 * i + 1];
            v2 += (double)gp[4 * i + 2];
            v3 += (double)gp[4 * i + 3];
        }
        v0 = warp_sum_d(v0); v1 = warp_sum_d(v1);
        v2 = warp_sum_d(v2); v3 = warp_sum_d(v3);

        __shared__ double smd[NT / 32][4];
        if (lane == 0) { smd[w][0] = v0; smd[w][1] = v1; smd[w][2] = v2; smd[w][3] = v3; }
        __syncthreads();
        if (w == 0) {
            double a = (lane < NT / 32) ? smd[lane][0] : 0.0;
            double b = (lane < NT / 32) ? smd[lane][1] : 0.0;
            double c = (lane < NT / 32) ? smd[lane][2] : 0.0;
            double d = (lane < NT / 32) ? smd[lane][3] : 0.0;
            a = warp_sum_d(a); b = warp_sum_d(b);
            c = warp_sum_d(c); d = warp_sum_d(d);
            if (lane == 0) {
                double coord = 5.0 * a;   // LAMBDA_COORD
                double objl  = b;
                double noobj = 0.5 * c;   // LAMBDA_NOOBJ
                double cls   = d;
                out[0] = (float)(coord * (double)inv_bs);
                out[1] = (float)(objl  * (double)inv_bs);
                out[2] = (float)(noobj * (double)inv_bs);
                out[3] = (float)(cls   * (double)inv_bs);
                out[4] = (float)((coord + objl + noobj + cls) * (double)inv_bs);
                g_count = 0;              // reset for next graph replay
            }
        }
    }
}

extern "C" void kernel_launch(void* const* d_in, const int* in_sizes, int n_in,
                              void* d_out, int out_size) {
    const float* pred   = (const float*)d_in[0];
    const float* target = (const float*)d_in[1];
    float* out = (float*)d_out;

    int total   = in_sizes[0];                       // batch * 49 * 30
    int ncells  = total / CH;                        // batch * 49
    int batch   = ncells / CELLS_PB;
    int nchunks = (ncells + CELLS_CHUNK - 1) / CELLS_CHUNK;   // 3136
    int nblocks = nchunks < TARGET_BLOCKS ? nchunks : TARGET_BLOCKS;
    if (nblocks > MAXBLOCKS) nblocks = MAXBLOCKS;
    float inv_bs = 1.0f / (float)batch;

    cudaFuncSetAttribute(yolo_staged_kernel,
                         cudaFuncAttributeMaxDynamicSharedMemorySize, SMEM_BYTES);
    yolo_staged_kernel<<<nblocks, NT, SMEM_BYTES>>>(pred, target, ncells, nchunks,
                                                    inv_bs, out);
}